// round 15
// baseline (speedup 1.0000x reference)
#include <cuda_runtime.h>
#include <cuda_bf16.h>
#include <cuda_fp16.h>
#include <cstdint>

// Problem dims (fixed by the dataset)
#define BB     8
#define FF     8192
#define NLAT   64
#define DD     1024
#define HH     8
#define DHD    64
#define INNER  512
#define KVLEN  (FF + NLAT)          // 8256
#define MROWS  (BB * KVLEN)         // 66048
#define NSPLIT 16
#define JT     64                    // kv tile in attention
#define NTILES (KVLEN / JT)          // 129
#define TPS    ((NTILES + NSPLIT - 1) / NSPLIT)  // 9
#define LN_EPS 1e-5f

// ---------------- family-safe PTX helpers (sm_80-era; no 'a'-features) ------
__device__ __forceinline__ uint32_t smem_u32(const void* p) {
    uint32_t a;
    asm("{ .reg .u64 t; cvta.to.shared.u64 t, %1; cvt.u32.u64 %0, t; }" : "=r"(a) : "l"(p));
    return a;
}
__device__ __forceinline__ void cp_async16(uint32_t dst, const void* src) {
    asm volatile("cp.async.cg.shared.global [%0], [%1], 16;" :: "r"(dst), "l"(src));
}
#define CP_COMMIT() asm volatile("cp.async.commit_group;" ::: "memory")
#define CP_WAIT(n)  asm volatile("cp.async.wait_group %0;" :: "n"(n) : "memory")

__device__ __forceinline__ void ldsm_x4(uint32_t* r, uint32_t addr) {
    asm volatile("ldmatrix.sync.aligned.m8n8.x4.shared.b16 {%0,%1,%2,%3}, [%4];"
        : "=r"(r[0]), "=r"(r[1]), "=r"(r[2]), "=r"(r[3]) : "r"(addr));
}
__device__ __forceinline__ void ldsm_x4_trans(uint32_t* r, uint32_t addr) {
    asm volatile("ldmatrix.sync.aligned.m8n8.x4.trans.shared.b16 {%0,%1,%2,%3}, [%4];"
        : "=r"(r[0]), "=r"(r[1]), "=r"(r[2]), "=r"(r[3]) : "r"(addr));
}
// fp16 mma
__device__ __forceinline__ void mma16816h(float* c, const uint32_t* a,
                                          uint32_t b0, uint32_t b1) {
    asm volatile(
        "mma.sync.aligned.m16n8k16.row.col.f32.f16.f16.f32 "
        "{%0,%1,%2,%3}, {%4,%5,%6,%7}, {%8,%9}, {%0,%1,%2,%3};"
        : "+f"(c[0]), "+f"(c[1]), "+f"(c[2]), "+f"(c[3])
        : "r"(a[0]), "r"(a[1]), "r"(a[2]), "r"(a[3]), "r"(b0), "r"(b1));
}

// -------- scratch (device globals; no allocations allowed) --------
__device__ float          g_lat_ln[BB * NLAT * DD];                       // 2 MB
__device__ __half         g_af[(size_t)MROWS * DD];                       // 135 MB (A fp16)
__device__ __half         g_bf[1024 * 1024];                              // 2 MB  [n][k] fp16
__device__ __half         g_kvf[(size_t)MROWS * 1024];                    // 135 MB (cols 0-511 K, 512-1023 V)
__device__ float          g_qmat[BB * NLAT * INNER];                      // 1 MB
__device__ float          g_attnout[BB * NLAT * INNER];                   // 1 MB
__device__ float          g_pacc[(size_t)BB * HH * NSPLIT * NLAT * DHD];  // 16.8 MB
__device__ float          g_pm[BB * HH * NSPLIT * NLAT];
__device__ float          g_pl[BB * HH * NSPLIT * NLAT];
__device__ int            g_mask_is_byte;

// ---- LayerNorm of latents + (block 0) mask dtype detection ----
__global__ __launch_bounds__(256) void ln_lat_kernel(const float* __restrict__ lat,
                                                     const float* __restrict__ gamma,
                                                     const float* __restrict__ beta,
                                                     const unsigned int* __restrict__ mask_w) {
    int row = blockIdx.x;
    int t = threadIdx.x;
    if (row == 0 && t == 0) {
        unsigned int acc = 0;
        #pragma unroll
        for (int i = 0; i < 64; i++) acc |= mask_w[i];
        g_mask_is_byte = (acc > 1u) ? 1 : 0;
    }
    float4 v = ((const float4*)(lat + (size_t)row * DD))[t];
    __shared__ float rs[256], rq[256];
    rs[t] = v.x + v.y + v.z + v.w;
    rq[t] = v.x*v.x + v.y*v.y + v.z*v.z + v.w*v.w;
    __syncthreads();
    for (int off = 128; off > 0; off >>= 1) {
        if (t < off) { rs[t] += rs[t + off]; rq[t] += rq[t + off]; }
        __syncthreads();
    }
    float mu   = rs[0] * (1.f / DD);
    float var  = rq[0] * (1.f / DD) - mu * mu;
    float rstd = rsqrtf(var + LN_EPS);
    float4 gv = ((const float4*)gamma)[t];
    float4 bv = ((const float4*)beta)[t];
    float4 o;
    o.x = (v.x - mu) * rstd * gv.x + bv.x;
    o.y = (v.y - mu) * rstd * gv.y + bv.y;
    o.z = (v.z - mu) * rstd * gv.z + bv.z;
    o.w = (v.w - mu) * rstd * gv.w + bv.w;
    ((float4*)(g_lat_ln + (size_t)row * DD))[t] = o;
}

// ---- fused LN + fp16 store of A: one row per warp, shuffle reduction ----
__global__ __launch_bounds__(256) void prep_a_kernel(const float* __restrict__ x,
                                                     const float* __restrict__ gm_,
                                                     const float* __restrict__ bm_,
                                                     const float* __restrict__ gate_p) {
    int wid = threadIdx.x >> 5, lane = threadIdx.x & 31;
    int row = blockIdx.x * 8 + wid;       // 0..MROWS-1 (grid = MROWS/8)
    int b = row / KVLEN;
    int r = row - b * KVLEN;
    float4 v[8];
    const float4* src;
    if (r < FF) src = (const float4*)(x + ((size_t)b * FF + r) * DD);
    else        src = (const float4*)(g_lat_ln + ((size_t)b * NLAT + (r - FF)) * DD);
    #pragma unroll
    for (int i = 0; i < 8; i++) v[i] = src[lane + 32 * i];

    if (r < FF) {
        float s = 0.f, q = 0.f;
        #pragma unroll
        for (int i = 0; i < 8; i++) {
            s += v[i].x + v[i].y + v[i].z + v[i].w;
            q += v[i].x*v[i].x + v[i].y*v[i].y + v[i].z*v[i].z + v[i].w*v[i].w;
        }
        #pragma unroll
        for (int off = 16; off > 0; off >>= 1) {
            s += __shfl_xor_sync(0xffffffffu, s, off);
            q += __shfl_xor_sync(0xffffffffu, q, off);
        }
        float mu   = s * (1.f / DD);
        float var  = q * (1.f / DD) - mu * mu;
        float rstd = rsqrtf(var + LN_EPS);
        #pragma unroll
        for (int i = 0; i < 8; i++) {
            float4 gv = ((const float4*)gm_)[lane + 32 * i];
            float4 bv = ((const float4*)bm_)[lane + 32 * i];
            v[i].x = (v[i].x - mu) * rstd * gv.x + bv.x;
            v[i].y = (v[i].y - mu) * rstd * gv.y + bv.y;
            v[i].z = (v[i].z - mu) * rstd * gv.z + bv.z;
            v[i].w = (v[i].w - mu) * rstd * gv.w + bv.w;
        }
    } else {
        float gate = gate_p[0];
        #pragma unroll
        for (int i = 0; i < 8; i++) {
            v[i].x *= gate; v[i].y *= gate; v[i].z *= gate; v[i].w *= gate;
        }
    }
    uint2* dst = (uint2*)(g_af + (size_t)row * DD);
    #pragma unroll
    for (int i = 0; i < 8; i++) {
        __half2 h01 = __floats2half2_rn(v[i].x, v[i].y);
        __half2 h23 = __floats2half2_rn(v[i].z, v[i].w);
        uint2 u;
        u.x = *(uint32_t*)&h01;
        u.y = *(uint32_t*)&h23;
        dst[lane + 32 * i] = u;
    }
}

// ---- transpose [Wk|Wv] (k-major [1024][512] each) into B[n][k] fp16 ----
__global__ __launch_bounds__(256) void prep_w_kernel(const float* __restrict__ Wk,
                                                     const float* __restrict__ Wv) {
    __shared__ float tile[32][33];
    int n0 = blockIdx.x * 32;           // 0..1023 (n of concat)
    int k0 = blockIdx.y * 32;
    int tx = threadIdx.x & 31, ty = threadIdx.x >> 5;  // 32 x 8
    const float* W = (n0 < 512) ? Wk : Wv;
    int nn0 = (n0 < 512) ? n0 : (n0 - 512);
    for (int i = ty; i < 32; i += 8)
        tile[i][tx] = W[(size_t)(k0 + i) * 512 + nn0 + tx];
    __syncthreads();
    for (int i = ty; i < 32; i += 8) {
        float v = tile[tx][i];          // = W[k0+tx][nn0+i]
        g_bf[(size_t)(n0 + i) * 1024 + k0 + tx] = __float2half_rn(v);
    }
}

// ---- HMMA (mma.sync fp16, 1-term) K/V projection: kv = A @ B^T ----
// Legacy-HMMA issue-bound at ~545 us (~92% of the fallback pipe); config is
// the measured local optimum: BM=BN=128, BK=32, 8 warps 32x64, 2 CTAs/SM,
// 5-stage pipeline, prefetch distance 4.
#define AS_STRIDE_H 40                      // halves per SMEM row
#define MAT_BYTES   (128 * AS_STRIDE_H * 2) // 10240 per matrix tile
#define STG_BYTES   (2 * MAT_BYTES)         // 20480 per stage (A, B)
#define NSTAGE      5
#define GEMM_SMEM   (NSTAGE * STG_BYTES)    // 102400
#define NCHUNK      32

__global__ __launch_bounds__(256, 2) void kv_mma_kernel() {
    extern __shared__ char smem[];
    const uint32_t sbase = smem_u32(smem);
    const int t = threadIdx.x;
    const int wid = t >> 5, lane = t & 31;
    const int ntile = blockIdx.x;            // 0..7
    const int mtile = blockIdx.y;            // 0..515
    const size_t arow0 = (size_t)mtile * 128;
    const int    brow0 = ntile * 128;

    // global load assignment: row r_ld, two consecutive 16B segs
    const int r_ld = t >> 1;
    const int seg0 = (t & 1) * 2;            // 0 or 2 (of 4 segs/row)
    const __half* gA = g_af + (arow0 + r_ld) * 1024 + seg0 * 8;
    const __half* gB = g_bf + (size_t)(brow0 + r_ld) * 1024 + seg0 * 8;
    const uint32_t sAdst = sbase + r_ld * 80 + seg0 * 16;

    #define LOAD_CHUNK(chunk, stg_) do {                                       \
        uint32_t sb_ = sAdst + (stg_) * STG_BYTES;                             \
        int ko_ = (chunk) * 32;                                                \
        cp_async16(sb_,                  gA + ko_);                            \
        cp_async16(sb_ + 16,             gA + ko_ + 8);                        \
        cp_async16(sb_ + MAT_BYTES,      gB + ko_);                            \
        cp_async16(sb_ + MAT_BYTES + 16, gB + ko_ + 8);                        \
    } while (0)

    // warp tile: wm in {0,32,64,96}, wn in {0,64}
    const int wm = (wid & 3) * 32;
    const int wn = (wid >> 2) * 64;

    const int a_off_h = (wm + (lane & 15)) * AS_STRIDE_H + (lane >> 4) * 8;
    const int b_off_h = (wn + (lane & 7) + ((lane >> 3) & 1) * 8) * AS_STRIDE_H
                        + (lane >> 4) * 8;

    float acc[2][8][4];
    #pragma unroll
    for (int i = 0; i < 2; i++)
        #pragma unroll
        for (int j = 0; j < 8; j++)
            #pragma unroll
            for (int c = 0; c < 4; c++) acc[i][j][c] = 0.f;

    LOAD_CHUNK(0, 0); CP_COMMIT();
    LOAD_CHUNK(1, 1); CP_COMMIT();
    LOAD_CHUNK(2, 2); CP_COMMIT();
    LOAD_CHUNK(3, 3); CP_COMMIT();

    int st = 0;  // stage of current chunk
    for (int chunk = 0; chunk < NCHUNK; chunk++) {
        if (chunk < NCHUNK - 3)       { CP_WAIT(3); }
        else if (chunk == NCHUNK - 3) { CP_WAIT(2); }
        else if (chunk == NCHUNK - 2) { CP_WAIT(1); }
        else                          { CP_WAIT(0); }
        __syncthreads();   // also protects WAR on the stage being refilled
        if (chunk + 4 < NCHUNK) {
            int stn = st + 4; if (stn >= NSTAGE) stn -= NSTAGE;
            LOAD_CHUNK(chunk + 4, stn);
            CP_COMMIT();
        }

        const uint32_t stg = sbase + st * STG_BYTES;
        #pragma unroll
        for (int ks = 0; ks < 2; ks++) {
            uint32_t a[2][4];
            #pragma unroll
            for (int mi = 0; mi < 2; mi++) {
                uint32_t ao = stg + (a_off_h + mi * 16 * AS_STRIDE_H + ks * 16) * 2;
                ldsm_x4(a[mi], ao);
            }
            #pragma unroll
            for (int nip = 0; nip < 4; nip++) {
                uint32_t bb[4];
                uint32_t bo = stg + MAT_BYTES
                            + (b_off_h + nip * 16 * AS_STRIDE_H + ks * 16) * 2;
                ldsm_x4(bb, bo);
                #pragma unroll
                for (int mi = 0; mi < 2; mi++) {
                    mma16816h(acc[mi][nip * 2],     a[mi], bb[0], bb[2]);
                    mma16816h(acc[mi][nip * 2 + 1], a[mi], bb[1], bb[3]);
                }
            }
        }
        if (++st == NSTAGE) st = 0;
    }

    // epilogue: write kv as single fp16
    const int col0 = ntile * 128 + wn + (lane & 3) * 2;
    #pragma unroll
    for (int mi = 0; mi < 2; mi++) {
        size_t row = arow0 + wm + mi * 16 + (lane >> 2);
        #pragma unroll
        for (int ni = 0; ni < 8; ni++) {
            size_t o0 = row * 1024 + col0 + ni * 8;
            size_t o1 = (row + 8) * 1024 + col0 + ni * 8;
            *(__half2*)(g_kvf + o0) = __floats2half2_rn(acc[mi][ni][0], acc[mi][ni][1]);
            *(__half2*)(g_kvf + o1) = __floats2half2_rn(acc[mi][ni][2], acc[mi][ni][3]);
        }
    }
}

// ---- generic small sgemm (mode 0: Q proj, mode 1: out proj) ----
__global__ __launch_bounds__(256) void sgemm_kernel(const float* __restrict__ Bmat,
                                                    float* __restrict__ Cext,
                                                    int M, int N, int K,
                                                    int lda, int ldb, int ldc,
                                                    float alpha, int mode) {
    const float* A = (mode == 0) ? g_lat_ln : g_attnout;
    float* C = (mode == 0) ? g_qmat : Cext;
    __shared__ float As[16][65];
    __shared__ float Bs[16][65];
    int t = threadIdx.x;
    int tx = t & 15, ty = t >> 4;
    int n0 = blockIdx.x * 64;
    int m0 = blockIdx.y * 64;
    float acc[4][4] = {};
    for (int k0 = 0; k0 < K; k0 += 16) {
        #pragma unroll
        for (int l = 0; l < 4; l++) {
            int idx = t + l * 256;
            int row = idx >> 4, kk = idx & 15;
            As[kk][row] = A[(size_t)(m0 + row) * lda + k0 + kk];
        }
        #pragma unroll
        for (int l = 0; l < 4; l++) {
            int idx = t + l * 256;
            int kk = idx >> 6, col = idx & 63;
            Bs[kk][col] = Bmat[(size_t)(k0 + kk) * ldb + n0 + col];
        }
        __syncthreads();
        #pragma unroll
        for (int kk = 0; kk < 16; kk++) {
            float a[4], bb[4];
            #pragma unroll
            for (int i = 0; i < 4; i++) a[i]  = As[kk][ty * 4 + i];
            #pragma unroll
            for (int j = 0; j < 4; j++) bb[j] = Bs[kk][tx * 4 + j];
            #pragma unroll
            for (int i = 0; i < 4; i++)
                #pragma unroll
                for (int j = 0; j < 4; j++)
                    acc[i][j] = fmaf(a[i], bb[j], acc[i][j]);
        }
        __syncthreads();
    }
    #pragma unroll
    for (int i = 0; i < 4; i++)
        #pragma unroll
        for (int j = 0; j < 4; j++)
            C[(size_t)(m0 + ty * 4 + i) * ldc + n0 + tx * 4 + j] = alpha * acc[i][j];
}

// ---- split-KV flash attention, fp16 HMMA, JT=64 ----
// Q split fp16 hi/lo (exact to 2^-22); K,V single fp16; P split fp16 hi/lo.
// Softmax bookkeeping parallelized: 4 threads per q-row + shfl reduce;
// l-update fused into phase 4 (old 64-thread serial phases eliminated).
#define ATT_QSTR 72
#define ATT_KSTR 72
#define ATT_PSTR 72
#define ATT_SSTR 72
#define AOFF_QH 0
#define AOFF_QL 9216
#define AOFF_K  18432
#define AOFF_V  27648
#define AOFF_SP 36864
#define AOFF_PH 55296
#define AOFF_PL 64512
#define AOFF_M  73728
#define AOFF_L  73984
#define AOFF_AL 74240
#define AOFF_MN 74496
#define AOFF_VD 74752
#define ATT_SMEM 75008

__global__ __launch_bounds__(256) void attn_mma_kernel(const void* __restrict__ mask_raw) {
    extern __shared__ char sm[];
    const uint32_t sb = smem_u32(sm);
    const int split = blockIdx.x, h = blockIdx.y, b = blockIdx.z;
    const int t = threadIdx.x, wid = t >> 5, lane = t & 31;
    const unsigned char* mask8 = (const unsigned char*)mask_raw;
    const int*           mask32 = (const int*)mask_raw;
    const int is_byte = g_mask_is_byte;

    float* mf  = (float*)(sm + AOFF_M);
    float* lf  = (float*)(sm + AOFF_L);
    float* alf = (float*)(sm + AOFF_AL);
    float* mnf = (float*)(sm + AOFF_MN);
    float* vdf = (float*)(sm + AOFF_VD);

    // prologue: load+split Q slice (64q x 64d) to Qh/Ql (fp16 hi/lo)
    {
        int q = t >> 2, dg = (t & 3) * 16;
        const float4* src = (const float4*)(g_qmat + ((size_t)(b * NLAT + q)) * INNER
                                            + h * DHD + dg);
        __half2* qh = (__half2*)(sm + AOFF_QH + (q * ATT_QSTR + dg) * 2);
        __half2* ql = (__half2*)(sm + AOFF_QL + (q * ATT_QSTR + dg) * 2);
        #pragma unroll
        for (int i = 0; i < 4; i++) {
            float4 v = src[i];
            __half2 h01 = __floats2half2_rn(v.x, v.y);
            __half2 h23 = __floats2half2_rn(v.z, v.w);
            __half2 l01 = __floats2half2_rn(v.x - __half2float(__low2half(h01)),
                                            v.y - __half2float(__high2half(h01)));
            __half2 l23 = __floats2half2_rn(v.z - __half2float(__low2half(h23)),
                                            v.w - __half2float(__high2half(h23)));
            qh[i * 2] = h01; qh[i * 2 + 1] = h23;
            ql[i * 2] = l01; ql[i * 2 + 1] = l23;
        }
    }
    if (t < 64) { mf[t] = -1e30f; lf[t] = 0.f; }

    float acc[4][4];
    #pragma unroll
    for (int i = 0; i < 4; i++)
        #pragma unroll
        for (int j = 0; j < 4; j++) acc[i][j] = 0.f;

    const int t0 = split * TPS;
    int tcnt = NTILES - t0;
    if (tcnt > TPS) tcnt = TPS;
    if (tcnt < 0) tcnt = 0;
    __syncthreads();

    for (int it = 0; it < tcnt; it++) {
        const int j0 = (t0 + it) * JT;
        // phase 1: K/V fp16 tiles (64 rows x 64 cols each), 2 segs/thread/array
        {
            int seg = (t & 7) * 8;         // halves
            #pragma unroll
            for (int it2 = 0; it2 < 2; it2++) {
                int row = (t >> 3) + it2 * 32;
                const __half* src = g_kvf + ((size_t)b * KVLEN + j0 + row) * 1024;
                uint32_t doff = (uint32_t)(row * ATT_KSTR + seg) * 2;
                *(uint4*)(sm + AOFF_K + doff) = *(const uint4*)(src + h * DHD + seg);
                *(uint4*)(sm + AOFF_V + doff) = *(const uint4*)(src + 512 + h * DHD + seg);
            }
        }
        if (t < JT) {
            int row = j0 + t;
            bool valid;
            if (row >= FF) valid = true;
            else {
                int mv = is_byte ? (int)mask8[b * FF + row] : mask32[b * FF + row];
                valid = (mv == 0);
            }
            vdf[t] = valid ? 1.f : 0.f;
        }
        __syncthreads();

        // phase 2: S = Q K^T (2-term fp16), warp tile 16q x 32j, write SP[q][j]
        {
            const int wq = (wid & 3) * 16, wj = (wid >> 2) * 32;
            float c[4][4];
            #pragma unroll
            for (int jb = 0; jb < 4; jb++)
                #pragma unroll
                for (int cc2 = 0; cc2 < 4; cc2++) c[jb][cc2] = 0.f;
            #pragma unroll
            for (int ks = 0; ks < 4; ks++) {
                uint32_t aqh[4], aql[4], bk0[4], bk1[4];
                uint32_t aoff = ((wq + (lane & 15)) * ATT_QSTR + ks * 16
                                 + (lane >> 4) * 8) * 2;
                ldsm_x4(aqh, sb + AOFF_QH + aoff);
                ldsm_x4(aql, sb + AOFF_QL + aoff);
                uint32_t brow = (lane & 7) + ((lane >> 3) & 1) * 8;
                uint32_t bo0 = ((wj + brow) * ATT_KSTR + ks * 16 + (lane >> 4) * 8) * 2;
                uint32_t bo1 = ((wj + 16 + brow) * ATT_KSTR + ks * 16 + (lane >> 4) * 8) * 2;
                ldsm_x4(bk0, sb + AOFF_K + bo0);
                ldsm_x4(bk1, sb + AOFF_K + bo1);
                mma16816h(c[0], aqh, bk0[0], bk0[2]);
                mma16816h(c[0], aql, bk0[0], bk0[2]);
                mma16816h(c[1], aqh, bk0[1], bk0[3]);
                mma16816h(c[1], aql, bk0[1], bk0[3]);
                mma16816h(c[2], aqh, bk1[0], bk1[2]);
                mma16816h(c[2], aql, bk1[0], bk1[2]);
                mma16816h(c[3], aqh, bk1[1], bk1[3]);
                mma16816h(c[3], aql, bk1[1], bk1[3]);
            }
            float* sp = (float*)(sm + AOFF_SP);
            int r = lane >> 2, cc = (lane & 3) * 2;
            #pragma unroll
            for (int jb = 0; jb < 4; jb++) {
                *(float2*)&sp[(wq + r) * ATT_SSTR + wj + jb * 8 + cc] =
                    make_float2(c[jb][0], c[jb][1]);
                *(float2*)&sp[(wq + r + 8) * ATT_SSTR + wj + jb * 8 + cc] =
                    make_float2(c[jb][2], c[jb][3]);
            }
        }
        __syncthreads();

        // phase 3: masked row max -> mnew, alpha (4 threads/row + shfl)
        {
            int q = t >> 2, jg = (t & 3) * 16;
            const float* sp = (const float*)(sm + AOFF_SP) + q * ATT_SSTR + jg;
            float mx = -1e30f;
            #pragma unroll
            for (int i = 0; i < 16; i++)
                mx = fmaxf(mx, (vdf[jg + i] != 0.f) ? sp[i] : -1e30f);
            mx = fmaxf(mx, __shfl_xor_sync(0xffffffffu, mx, 1));
            mx = fmaxf(mx, __shfl_xor_sync(0xffffffffu, mx, 2));
            if ((t & 3) == 0) {
                float mold = mf[q];
                float mnew = fmaxf(mold, mx);
                mnf[q] = mnew;
                alf[q] = __expf(mold - mnew);
                mf[q]  = mnew;
            }
        }
        __syncthreads();

        // phase 4: P = exp(S - mnew) masked; split Ph/Pl; fused l-update; acc*=alpha
        {
            int q = t >> 2, jg = (t & 3) * 16;
            float* sp = (float*)(sm + AOFF_SP) + q * ATT_SSTR + jg;
            float mn = mnf[q];
            __half2* ph = (__half2*)(sm + AOFF_PH + (q * ATT_PSTR + jg) * 2);
            __half2* pl = (__half2*)(sm + AOFF_PL + (q * ATT_PSTR + jg) * 2);
            float psum = 0.f;
            #pragma unroll
            for (int i = 0; i < 16; i += 2) {
                float e0 = (vdf[jg + i]     != 0.f) ? __expf(sp[i]     - mn) : 0.f;
                float e1 = (vdf[jg + i + 1] != 0.f) ? __expf(sp[i + 1] - mn) : 0.f;
                psum += e0 + e1;
                __half2 hh = __floats2half2_rn(e0, e1);
                __half2 ll = __floats2half2_rn(e0 - __half2float(__low2half(hh)),
                                               e1 - __half2float(__high2half(hh)));
                ph[i >> 1] = hh; pl[i >> 1] = ll;
            }
            psum += __shfl_xor_sync(0xffffffffu, psum, 1);
            psum += __shfl_xor_sync(0xffffffffu, psum, 2);
            if ((t & 3) == 0) lf[q] = lf[q] * alf[q] + psum;
            const int wq = (wid & 3) * 16;
            float a1 = alf[wq + (lane >> 2)];
            float a2 = alf[wq + (lane >> 2) + 8];
            #pragma unroll
            for (int ni = 0; ni < 4; ni++) {
                acc[ni][0] *= a1; acc[ni][1] *= a1;
                acc[ni][2] *= a2; acc[ni][3] *= a2;
            }
        }
        __syncthreads();

        // phase 5: O += P V (2-term fp16, K-dim 64)
        {
            const int wq = (wid & 3) * 16, wd = (wid >> 2) * 32;
            #pragma unroll
            for (int ks = 0; ks < 4; ks++) {
                uint32_t aph[4], apl[4], bv0[4], bv1[4];
                uint32_t aoff = ((wq + (lane & 15)) * ATT_PSTR + ks * 16
                                 + (lane >> 4) * 8) * 2;
                ldsm_x4(aph, sb + AOFF_PH + aoff);
                ldsm_x4(apl, sb + AOFF_PL + aoff);
                uint32_t vrow = ks * 16 + (lane & 15);
                uint32_t v0 = (vrow * ATT_KSTR + wd + (lane >> 4) * 8) * 2;
                uint32_t v1 = (vrow * ATT_KSTR + wd + 16 + (lane >> 4) * 8) * 2;
                ldsm_x4_trans(bv0, sb + AOFF_V + v0);
                ldsm_x4_trans(bv1, sb + AOFF_V + v1);
                mma16816h(acc[0], aph, bv0[0], bv0[1]);
                mma16816h(acc[0], apl, bv0[0], bv0[1]);
                mma16816h(acc[1], aph, bv0[2], bv0[3]);
                mma16816h(acc[1], apl, bv0[2], bv0[3]);
                mma16816h(acc[2], aph, bv1[0], bv1[1]);
                mma16816h(acc[2], apl, bv1[0], bv1[1]);
                mma16816h(acc[3], aph, bv1[2], bv1[3]);
                mma16816h(acc[3], apl, bv1[2], bv1[3]);
            }
        }
        __syncthreads();
    }

    // epilogue: write partials
    {
        const int wq = (wid & 3) * 16, wd = (wid >> 2) * 32;
        size_t pbase = ((((size_t)b * HH + h) * NSPLIT + split) * NLAT) * (size_t)DHD;
        int r = lane >> 2, cc = (lane & 3) * 2;
        #pragma unroll
        for (int ni = 0; ni < 4; ni++) {
            float* d0 = g_pacc + pbase + (size_t)(wq + r) * DHD + wd + ni * 8 + cc;
            float* d1 = g_pacc + pbase + (size_t)(wq + r + 8) * DHD + wd + ni * 8 + cc;
            *(float2*)d0 = make_float2(acc[ni][0], acc[ni][1]);
            *(float2*)d1 = make_float2(acc[ni][2], acc[ni][3]);
        }
    }
    if (t < 64) {
        size_t sbi = (((size_t)b * HH + h) * NSPLIT + split) * NLAT + t;
        g_pm[sbi] = mf[t];
        g_pl[sbi] = lf[t];
    }
}

// ---- pass B: combine split partials -> attn output (b, q, h*64+d) ----
__global__ __launch_bounds__(64) void attn_combine_kernel() {
    int q = blockIdx.x, h = blockIdx.y, b = blockIdx.z;
    int d = threadIdx.x;
    size_t sb = (((size_t)b * HH + h) * NSPLIT) * NLAT + q;
    float mg = -1e30f;
    #pragma unroll
    for (int s = 0; s < NSPLIT; s++) mg = fmaxf(mg, g_pm[sb + (size_t)s * NLAT]);
    float denom = 0.f, a = 0.f;
    #pragma unroll
    for (int s = 0; s < NSPLIT; s++) {
        float w = __expf(g_pm[sb + (size_t)s * NLAT] - mg);
        denom += g_pl[sb + (size_t)s * NLAT] * w;
        a += g_pacc[((((size_t)b * HH + h) * NSPLIT + s) * NLAT + q) * DHD + d] * w;
    }
    g_attnout[((size_t)b * NLAT + q) * INNER + h * DHD + d] = a / denom;
}

extern "C" void kernel_launch(void* const* d_in, const int* in_sizes, int n_in,
                              void* d_out, int out_size) {
    const float* x    = (const float*)d_in[0];
    const float* lat  = (const float*)d_in[1];
    const void*  mask = d_in[2];
    const float* gate = (const float*)d_in[3];
    const float* gm   = (const float*)d_in[4];
    const float* bm   = (const float*)d_in[5];
    const float* gl   = (const float*)d_in[6];
    const float* bl   = (const float*)d_in[7];
    const float* Wq   = (const float*)d_in[8];
    const float* Wk   = (const float*)d_in[9];
    const float* Wv   = (const float*)d_in[10];
    const float* Wout = (const float*)d_in[11];
    float* out = (float*)d_out;

    // One-time setup (first call happens OUTSIDE graph capture: the harness's
    // correctness run). No device-memory allocation involved.
    static cudaStream_t s1 = nullptr;
    static cudaEvent_t evFork = nullptr, evJoin = nullptr;
    if (s1 == nullptr) {
        cudaStreamCreateWithFlags(&s1, cudaStreamNonBlocking);
        cudaEventCreateWithFlags(&evFork, cudaEventDisableTiming);
        cudaEventCreateWithFlags(&evJoin, cudaEventDisableTiming);
        cudaFuncSetAttribute(kv_mma_kernel,
                             cudaFuncAttributeMaxDynamicSharedMemorySize, GEMM_SMEM);
        cudaFuncSetAttribute(attn_mma_kernel,
                             cudaFuncAttributeMaxDynamicSharedMemorySize, ATT_SMEM);
    }

    // main stream: ln -> prep_a -> kv -> attn -> combine -> out
    // side stream: prep_w + Q-projection (independent of prep_a/kv), forked
    // after ln_lat, joined before kv_mma (kv needs g_bf; attn needs g_qmat).
    ln_lat_kernel<<<BB * NLAT, 256>>>(lat, gl, bl, (const unsigned int*)mask);
    cudaEventRecord(evFork, 0);
    cudaStreamWaitEvent(s1, evFork, 0);
    prep_w_kernel<<<dim3(32, 32), 256, 0, s1>>>(Wk, Wv);
    sgemm_kernel<<<dim3(INNER / 64, (BB * NLAT) / 64), 256, 0, s1>>>(
        Wq, nullptr, BB * NLAT, INNER, DD, DD, INNER, INNER, 0.125f, 0);
    cudaEventRecord(evJoin, s1);
    prep_a_kernel<<<MROWS / 8, 256>>>(x, gm, bm, gate);
    cudaStreamWaitEvent(0, evJoin, 0);
    kv_mma_kernel<<<dim3(8, 516), 256, GEMM_SMEM>>>();
    attn_mma_kernel<<<dim3(NSPLIT, HH, BB), 256, ATT_SMEM>>>(mask);
    attn_combine_kernel<<<dim3(NLAT, HH, BB), 64>>>();
    sgemm_kernel<<<dim3(DD / 64, (BB * NLAT) / 64), 256>>>(
        Wout, out, BB * NLAT, DD, INNER, INNER, DD, DD, 1.0f, 1);
}

// round 16
// speedup vs baseline: 1.0549x; 1.0549x over previous
#include <cuda_runtime.h>
#include <cuda_bf16.h>
#include <cuda_fp16.h>
#include <cstdint>

// Problem dims (fixed by the dataset)
#define BB     8
#define FF     8192
#define NLAT   64
#define DD     1024
#define HH     8
#define DHD    64
#define INNER  512
#define KVLEN  (FF + NLAT)          // 8256
#define MROWS  (BB * KVLEN)         // 66048
#define NSPLIT 16
#define JT     64                    // kv tile in attention
#define NTILES (KVLEN / JT)          // 129
#define TPS    ((NTILES + NSPLIT - 1) / NSPLIT)  // 9
#define LN_EPS 1e-5f

// ---------------- family-safe PTX helpers (sm_80-era; no 'a'-features) ------
__device__ __forceinline__ uint32_t smem_u32(const void* p) {
    uint32_t a;
    asm("{ .reg .u64 t; cvta.to.shared.u64 t, %1; cvt.u32.u64 %0, t; }" : "=r"(a) : "l"(p));
    return a;
}
__device__ __forceinline__ void cp_async16(uint32_t dst, const void* src) {
    asm volatile("cp.async.cg.shared.global [%0], [%1], 16;" :: "r"(dst), "l"(src));
}
#define CP_COMMIT() asm volatile("cp.async.commit_group;" ::: "memory")
#define CP_WAIT(n)  asm volatile("cp.async.wait_group %0;" :: "n"(n) : "memory")

__device__ __forceinline__ void ldsm_x4(uint32_t* r, uint32_t addr) {
    asm volatile("ldmatrix.sync.aligned.m8n8.x4.shared.b16 {%0,%1,%2,%3}, [%4];"
        : "=r"(r[0]), "=r"(r[1]), "=r"(r[2]), "=r"(r[3]) : "r"(addr));
}
__device__ __forceinline__ void ldsm_x4_trans(uint32_t* r, uint32_t addr) {
    asm volatile("ldmatrix.sync.aligned.m8n8.x4.trans.shared.b16 {%0,%1,%2,%3}, [%4];"
        : "=r"(r[0]), "=r"(r[1]), "=r"(r[2]), "=r"(r[3]) : "r"(addr));
}
// fp16 mma
__device__ __forceinline__ void mma16816h(float* c, const uint32_t* a,
                                          uint32_t b0, uint32_t b1) {
    asm volatile(
        "mma.sync.aligned.m16n8k16.row.col.f32.f16.f16.f32 "
        "{%0,%1,%2,%3}, {%4,%5,%6,%7}, {%8,%9}, {%0,%1,%2,%3};"
        : "+f"(c[0]), "+f"(c[1]), "+f"(c[2]), "+f"(c[3])
        : "r"(a[0]), "r"(a[1]), "r"(a[2]), "r"(a[3]), "r"(b0), "r"(b1));
}

// -------- scratch (device globals; no allocations allowed) --------
__device__ float          g_lat_ln[BB * NLAT * DD];                       // 2 MB
__device__ __half         g_af[(size_t)MROWS * DD];                       // 135 MB (A fp16)
__device__ __half         g_bf[1024 * 1024];                              // 2 MB  [n][k] fp16
__device__ __half         g_kvf[(size_t)MROWS * 1024];                    // 135 MB (cols 0-511 K, 512-1023 V)
__device__ float          g_qmat[BB * NLAT * INNER];                      // 1 MB
__device__ float          g_attnout[BB * NLAT * INNER];                   // 1 MB
__device__ float          g_pacc[(size_t)BB * HH * NSPLIT * NLAT * DHD];  // 16.8 MB
__device__ float          g_pm[BB * HH * NSPLIT * NLAT];
__device__ float          g_pl[BB * HH * NSPLIT * NLAT];
__device__ int            g_mask_is_byte;

// ---- LayerNorm of latents + (block 0) mask dtype detection ----
__global__ __launch_bounds__(256) void ln_lat_kernel(const float* __restrict__ lat,
                                                     const float* __restrict__ gamma,
                                                     const float* __restrict__ beta,
                                                     const unsigned int* __restrict__ mask_w) {
    int row = blockIdx.x;
    int t = threadIdx.x;
    if (row == 0 && t == 0) {
        unsigned int acc = 0;
        #pragma unroll
        for (int i = 0; i < 64; i++) acc |= mask_w[i];
        g_mask_is_byte = (acc > 1u) ? 1 : 0;
    }
    float4 v = ((const float4*)(lat + (size_t)row * DD))[t];
    __shared__ float rs[256], rq[256];
    rs[t] = v.x + v.y + v.z + v.w;
    rq[t] = v.x*v.x + v.y*v.y + v.z*v.z + v.w*v.w;
    __syncthreads();
    for (int off = 128; off > 0; off >>= 1) {
        if (t < off) { rs[t] += rs[t + off]; rq[t] += rq[t + off]; }
        __syncthreads();
    }
    float mu   = rs[0] * (1.f / DD);
    float var  = rq[0] * (1.f / DD) - mu * mu;
    float rstd = rsqrtf(var + LN_EPS);
    float4 gv = ((const float4*)gamma)[t];
    float4 bv = ((const float4*)beta)[t];
    float4 o;
    o.x = (v.x - mu) * rstd * gv.x + bv.x;
    o.y = (v.y - mu) * rstd * gv.y + bv.y;
    o.z = (v.z - mu) * rstd * gv.z + bv.z;
    o.w = (v.w - mu) * rstd * gv.w + bv.w;
    ((float4*)(g_lat_ln + (size_t)row * DD))[t] = o;
}

// ---- fused LN + fp16 store of A: one row per warp, shuffle reduction ----
__global__ __launch_bounds__(256) void prep_a_kernel(const float* __restrict__ x,
                                                     const float* __restrict__ gm_,
                                                     const float* __restrict__ bm_,
                                                     const float* __restrict__ gate_p) {
    int wid = threadIdx.x >> 5, lane = threadIdx.x & 31;
    int row = blockIdx.x * 8 + wid;       // 0..MROWS-1 (grid = MROWS/8)
    int b = row / KVLEN;
    int r = row - b * KVLEN;
    float4 v[8];
    const float4* src;
    if (r < FF) src = (const float4*)(x + ((size_t)b * FF + r) * DD);
    else        src = (const float4*)(g_lat_ln + ((size_t)b * NLAT + (r - FF)) * DD);
    #pragma unroll
    for (int i = 0; i < 8; i++) v[i] = src[lane + 32 * i];

    if (r < FF) {
        float s = 0.f, q = 0.f;
        #pragma unroll
        for (int i = 0; i < 8; i++) {
            s += v[i].x + v[i].y + v[i].z + v[i].w;
            q += v[i].x*v[i].x + v[i].y*v[i].y + v[i].z*v[i].z + v[i].w*v[i].w;
        }
        #pragma unroll
        for (int off = 16; off > 0; off >>= 1) {
            s += __shfl_xor_sync(0xffffffffu, s, off);
            q += __shfl_xor_sync(0xffffffffu, q, off);
        }
        float mu   = s * (1.f / DD);
        float var  = q * (1.f / DD) - mu * mu;
        float rstd = rsqrtf(var + LN_EPS);
        #pragma unroll
        for (int i = 0; i < 8; i++) {
            float4 gv = ((const float4*)gm_)[lane + 32 * i];
            float4 bv = ((const float4*)bm_)[lane + 32 * i];
            v[i].x = (v[i].x - mu) * rstd * gv.x + bv.x;
            v[i].y = (v[i].y - mu) * rstd * gv.y + bv.y;
            v[i].z = (v[i].z - mu) * rstd * gv.z + bv.z;
            v[i].w = (v[i].w - mu) * rstd * gv.w + bv.w;
        }
    } else {
        float gate = gate_p[0];
        #pragma unroll
        for (int i = 0; i < 8; i++) {
            v[i].x *= gate; v[i].y *= gate; v[i].z *= gate; v[i].w *= gate;
        }
    }
    uint2* dst = (uint2*)(g_af + (size_t)row * DD);
    #pragma unroll
    for (int i = 0; i < 8; i++) {
        __half2 h01 = __floats2half2_rn(v[i].x, v[i].y);
        __half2 h23 = __floats2half2_rn(v[i].z, v[i].w);
        uint2 u;
        u.x = *(uint32_t*)&h01;
        u.y = *(uint32_t*)&h23;
        dst[lane + 32 * i] = u;
    }
}

// ---- transpose [Wk|Wv] (k-major [1024][512] each) into B[n][k] fp16 ----
__global__ __launch_bounds__(256) void prep_w_kernel(const float* __restrict__ Wk,
                                                     const float* __restrict__ Wv) {
    __shared__ float tile[32][33];
    int n0 = blockIdx.x * 32;           // 0..1023 (n of concat)
    int k0 = blockIdx.y * 32;
    int tx = threadIdx.x & 31, ty = threadIdx.x >> 5;  // 32 x 8
    const float* W = (n0 < 512) ? Wk : Wv;
    int nn0 = (n0 < 512) ? n0 : (n0 - 512);
    for (int i = ty; i < 32; i += 8)
        tile[i][tx] = W[(size_t)(k0 + i) * 512 + nn0 + tx];
    __syncthreads();
    for (int i = ty; i < 32; i += 8) {
        float v = tile[tx][i];          // = W[k0+tx][nn0+i]
        g_bf[(size_t)(n0 + i) * 1024 + k0 + tx] = __float2half_rn(v);
    }
}

// ---- HMMA (mma.sync fp16, 1-term) K/V projection: kv = A @ B^T ----
// Legacy-HMMA issue-bound at ~545 us (~92% of the fallback pipe); config is
// the measured local optimum: BM=BN=128, BK=32, 8 warps 32x64, 2 CTAs/SM,
// 5-stage pipeline, prefetch distance 4.
#define AS_STRIDE_H 40                      // halves per SMEM row
#define MAT_BYTES   (128 * AS_STRIDE_H * 2) // 10240 per matrix tile
#define STG_BYTES   (2 * MAT_BYTES)         // 20480 per stage (A, B)
#define NSTAGE      5
#define GEMM_SMEM   (NSTAGE * STG_BYTES)    // 102400
#define NCHUNK      32

__global__ __launch_bounds__(256, 2) void kv_mma_kernel() {
    extern __shared__ char smem[];
    const uint32_t sbase = smem_u32(smem);
    const int t = threadIdx.x;
    const int wid = t >> 5, lane = t & 31;
    const int ntile = blockIdx.x;            // 0..7
    const int mtile = blockIdx.y;            // 0..515
    const size_t arow0 = (size_t)mtile * 128;
    const int    brow0 = ntile * 128;

    // global load assignment: row r_ld, two consecutive 16B segs
    const int r_ld = t >> 1;
    const int seg0 = (t & 1) * 2;            // 0 or 2 (of 4 segs/row)
    const __half* gA = g_af + (arow0 + r_ld) * 1024 + seg0 * 8;
    const __half* gB = g_bf + (size_t)(brow0 + r_ld) * 1024 + seg0 * 8;
    const uint32_t sAdst = sbase + r_ld * 80 + seg0 * 16;

    #define LOAD_CHUNK(chunk, stg_) do {                                       \
        uint32_t sb_ = sAdst + (stg_) * STG_BYTES;                             \
        int ko_ = (chunk) * 32;                                                \
        cp_async16(sb_,                  gA + ko_);                            \
        cp_async16(sb_ + 16,             gA + ko_ + 8);                        \
        cp_async16(sb_ + MAT_BYTES,      gB + ko_);                            \
        cp_async16(sb_ + MAT_BYTES + 16, gB + ko_ + 8);                        \
    } while (0)

    // warp tile: wm in {0,32,64,96}, wn in {0,64}
    const int wm = (wid & 3) * 32;
    const int wn = (wid >> 2) * 64;

    const int a_off_h = (wm + (lane & 15)) * AS_STRIDE_H + (lane >> 4) * 8;
    const int b_off_h = (wn + (lane & 7) + ((lane >> 3) & 1) * 8) * AS_STRIDE_H
                        + (lane >> 4) * 8;

    float acc[2][8][4];
    #pragma unroll
    for (int i = 0; i < 2; i++)
        #pragma unroll
        for (int j = 0; j < 8; j++)
            #pragma unroll
            for (int c = 0; c < 4; c++) acc[i][j][c] = 0.f;

    LOAD_CHUNK(0, 0); CP_COMMIT();
    LOAD_CHUNK(1, 1); CP_COMMIT();
    LOAD_CHUNK(2, 2); CP_COMMIT();
    LOAD_CHUNK(3, 3); CP_COMMIT();

    int st = 0;  // stage of current chunk
    for (int chunk = 0; chunk < NCHUNK; chunk++) {
        if (chunk < NCHUNK - 3)       { CP_WAIT(3); }
        else if (chunk == NCHUNK - 3) { CP_WAIT(2); }
        else if (chunk == NCHUNK - 2) { CP_WAIT(1); }
        else                          { CP_WAIT(0); }
        __syncthreads();   // also protects WAR on the stage being refilled
        if (chunk + 4 < NCHUNK) {
            int stn = st + 4; if (stn >= NSTAGE) stn -= NSTAGE;
            LOAD_CHUNK(chunk + 4, stn);
            CP_COMMIT();
        }

        const uint32_t stg = sbase + st * STG_BYTES;
        #pragma unroll
        for (int ks = 0; ks < 2; ks++) {
            uint32_t a[2][4];
            #pragma unroll
            for (int mi = 0; mi < 2; mi++) {
                uint32_t ao = stg + (a_off_h + mi * 16 * AS_STRIDE_H + ks * 16) * 2;
                ldsm_x4(a[mi], ao);
            }
            #pragma unroll
            for (int nip = 0; nip < 4; nip++) {
                uint32_t bb[4];
                uint32_t bo = stg + MAT_BYTES
                            + (b_off_h + nip * 16 * AS_STRIDE_H + ks * 16) * 2;
                ldsm_x4(bb, bo);
                #pragma unroll
                for (int mi = 0; mi < 2; mi++) {
                    mma16816h(acc[mi][nip * 2],     a[mi], bb[0], bb[2]);
                    mma16816h(acc[mi][nip * 2 + 1], a[mi], bb[1], bb[3]);
                }
            }
        }
        if (++st == NSTAGE) st = 0;
    }

    // epilogue: write kv as single fp16
    const int col0 = ntile * 128 + wn + (lane & 3) * 2;
    #pragma unroll
    for (int mi = 0; mi < 2; mi++) {
        size_t row = arow0 + wm + mi * 16 + (lane >> 2);
        #pragma unroll
        for (int ni = 0; ni < 8; ni++) {
            size_t o0 = row * 1024 + col0 + ni * 8;
            size_t o1 = (row + 8) * 1024 + col0 + ni * 8;
            *(__half2*)(g_kvf + o0) = __floats2half2_rn(acc[mi][ni][0], acc[mi][ni][1]);
            *(__half2*)(g_kvf + o1) = __floats2half2_rn(acc[mi][ni][2], acc[mi][ni][3]);
        }
    }
}

// ---- generic small sgemm (mode 0: Q proj, mode 1: out proj) ----
__global__ __launch_bounds__(256) void sgemm_kernel(const float* __restrict__ Bmat,
                                                    float* __restrict__ Cext,
                                                    int M, int N, int K,
                                                    int lda, int ldb, int ldc,
                                                    float alpha, int mode) {
    const float* A = (mode == 0) ? g_lat_ln : g_attnout;
    float* C = (mode == 0) ? g_qmat : Cext;
    __shared__ float As[16][65];
    __shared__ float Bs[16][65];
    int t = threadIdx.x;
    int tx = t & 15, ty = t >> 4;
    int n0 = blockIdx.x * 64;
    int m0 = blockIdx.y * 64;
    float acc[4][4] = {};
    for (int k0 = 0; k0 < K; k0 += 16) {
        #pragma unroll
        for (int l = 0; l < 4; l++) {
            int idx = t + l * 256;
            int row = idx >> 4, kk = idx & 15;
            As[kk][row] = A[(size_t)(m0 + row) * lda + k0 + kk];
        }
        #pragma unroll
        for (int l = 0; l < 4; l++) {
            int idx = t + l * 256;
            int kk = idx >> 6, col = idx & 63;
            Bs[kk][col] = Bmat[(size_t)(k0 + kk) * ldb + n0 + col];
        }
        __syncthreads();
        #pragma unroll
        for (int kk = 0; kk < 16; kk++) {
            float a[4], bb[4];
            #pragma unroll
            for (int i = 0; i < 4; i++) a[i]  = As[kk][ty * 4 + i];
            #pragma unroll
            for (int j = 0; j < 4; j++) bb[j] = Bs[kk][tx * 4 + j];
            #pragma unroll
            for (int i = 0; i < 4; i++)
                #pragma unroll
                for (int j = 0; j < 4; j++)
                    acc[i][j] = fmaf(a[i], bb[j], acc[i][j]);
        }
        __syncthreads();
    }
    #pragma unroll
    for (int i = 0; i < 4; i++)
        #pragma unroll
        for (int j = 0; j < 4; j++)
            C[(size_t)(m0 + ty * 4 + i) * ldc + n0 + tx * 4 + j] = alpha * acc[i][j];
}

// ---- split-KV flash attention, fp16 HMMA, JT=64 ----
// Q split fp16 hi/lo (exact to 2^-22); K,V single fp16; P split fp16 hi/lo.
// Softmax bookkeeping parallelized: 4 threads per q-row + shfl reduce;
// l-update fused into phase 4.
#define ATT_QSTR 72
#define ATT_KSTR 72
#define ATT_PSTR 72
#define ATT_SSTR 72
#define AOFF_QH 0
#define AOFF_QL 9216
#define AOFF_K  18432
#define AOFF_V  27648
#define AOFF_SP 36864
#define AOFF_PH 55296
#define AOFF_PL 64512
#define AOFF_M  73728
#define AOFF_L  73984
#define AOFF_AL 74240
#define AOFF_MN 74496
#define AOFF_VD 74752
#define ATT_SMEM 75008

__global__ __launch_bounds__(256) void attn_mma_kernel(const void* __restrict__ mask_raw) {
    extern __shared__ char sm[];
    const uint32_t sb = smem_u32(sm);
    const int split = blockIdx.x, h = blockIdx.y, b = blockIdx.z;
    const int t = threadIdx.x, wid = t >> 5, lane = t & 31;
    const unsigned char* mask8 = (const unsigned char*)mask_raw;
    const int*           mask32 = (const int*)mask_raw;
    const int is_byte = g_mask_is_byte;

    float* mf  = (float*)(sm + AOFF_M);
    float* lf  = (float*)(sm + AOFF_L);
    float* alf = (float*)(sm + AOFF_AL);
    float* mnf = (float*)(sm + AOFF_MN);
    float* vdf = (float*)(sm + AOFF_VD);

    // prologue: load+split Q slice (64q x 64d) to Qh/Ql (fp16 hi/lo)
    {
        int q = t >> 2, dg = (t & 3) * 16;
        const float4* src = (const float4*)(g_qmat + ((size_t)(b * NLAT + q)) * INNER
                                            + h * DHD + dg);
        __half2* qh = (__half2*)(sm + AOFF_QH + (q * ATT_QSTR + dg) * 2);
        __half2* ql = (__half2*)(sm + AOFF_QL + (q * ATT_QSTR + dg) * 2);
        #pragma unroll
        for (int i = 0; i < 4; i++) {
            float4 v = src[i];
            __half2 h01 = __floats2half2_rn(v.x, v.y);
            __half2 h23 = __floats2half2_rn(v.z, v.w);
            __half2 l01 = __floats2half2_rn(v.x - __half2float(__low2half(h01)),
                                            v.y - __half2float(__high2half(h01)));
            __half2 l23 = __floats2half2_rn(v.z - __half2float(__low2half(h23)),
                                            v.w - __half2float(__high2half(h23)));
            qh[i * 2] = h01; qh[i * 2 + 1] = h23;
            ql[i * 2] = l01; ql[i * 2 + 1] = l23;
        }
    }
    if (t < 64) { mf[t] = -1e30f; lf[t] = 0.f; }

    float acc[4][4];
    #pragma unroll
    for (int i = 0; i < 4; i++)
        #pragma unroll
        for (int j = 0; j < 4; j++) acc[i][j] = 0.f;

    const int t0 = split * TPS;
    int tcnt = NTILES - t0;
    if (tcnt > TPS) tcnt = TPS;
    if (tcnt < 0) tcnt = 0;
    __syncthreads();

    for (int it = 0; it < tcnt; it++) {
        const int j0 = (t0 + it) * JT;
        // phase 1: K/V fp16 tiles (64 rows x 64 cols each), 2 segs/thread/array
        {
            int seg = (t & 7) * 8;         // halves
            #pragma unroll
            for (int it2 = 0; it2 < 2; it2++) {
                int row = (t >> 3) + it2 * 32;
                const __half* src = g_kvf + ((size_t)b * KVLEN + j0 + row) * 1024;
                uint32_t doff = (uint32_t)(row * ATT_KSTR + seg) * 2;
                *(uint4*)(sm + AOFF_K + doff) = *(const uint4*)(src + h * DHD + seg);
                *(uint4*)(sm + AOFF_V + doff) = *(const uint4*)(src + 512 + h * DHD + seg);
            }
        }
        if (t < JT) {
            int row = j0 + t;
            bool valid;
            if (row >= FF) valid = true;
            else {
                int mv = is_byte ? (int)mask8[b * FF + row] : mask32[b * FF + row];
                valid = (mv == 0);
            }
            vdf[t] = valid ? 1.f : 0.f;
        }
        __syncthreads();

        // phase 2: S = Q K^T (2-term fp16), warp tile 16q x 32j, write SP[q][j]
        {
            const int wq = (wid & 3) * 16, wj = (wid >> 2) * 32;
            float c[4][4];
            #pragma unroll
            for (int jb = 0; jb < 4; jb++)
                #pragma unroll
                for (int cc2 = 0; cc2 < 4; cc2++) c[jb][cc2] = 0.f;
            #pragma unroll
            for (int ks = 0; ks < 4; ks++) {
                uint32_t aqh[4], aql[4], bk0[4], bk1[4];
                uint32_t aoff = ((wq + (lane & 15)) * ATT_QSTR + ks * 16
                                 + (lane >> 4) * 8) * 2;
                ldsm_x4(aqh, sb + AOFF_QH + aoff);
                ldsm_x4(aql, sb + AOFF_QL + aoff);
                uint32_t brow = (lane & 7) + ((lane >> 3) & 1) * 8;
                uint32_t bo0 = ((wj + brow) * ATT_KSTR + ks * 16 + (lane >> 4) * 8) * 2;
                uint32_t bo1 = ((wj + 16 + brow) * ATT_KSTR + ks * 16 + (lane >> 4) * 8) * 2;
                ldsm_x4(bk0, sb + AOFF_K + bo0);
                ldsm_x4(bk1, sb + AOFF_K + bo1);
                mma16816h(c[0], aqh, bk0[0], bk0[2]);
                mma16816h(c[0], aql, bk0[0], bk0[2]);
                mma16816h(c[1], aqh, bk0[1], bk0[3]);
                mma16816h(c[1], aql, bk0[1], bk0[3]);
                mma16816h(c[2], aqh, bk1[0], bk1[2]);
                mma16816h(c[2], aql, bk1[0], bk1[2]);
                mma16816h(c[3], aqh, bk1[1], bk1[3]);
                mma16816h(c[3], aql, bk1[1], bk1[3]);
            }
            float* sp = (float*)(sm + AOFF_SP);
            int r = lane >> 2, cc = (lane & 3) * 2;
            #pragma unroll
            for (int jb = 0; jb < 4; jb++) {
                *(float2*)&sp[(wq + r) * ATT_SSTR + wj + jb * 8 + cc] =
                    make_float2(c[jb][0], c[jb][1]);
                *(float2*)&sp[(wq + r + 8) * ATT_SSTR + wj + jb * 8 + cc] =
                    make_float2(c[jb][2], c[jb][3]);
            }
        }
        __syncthreads();

        // phase 3: masked row max -> mnew, alpha (4 threads/row + shfl)
        {
            int q = t >> 2, jg = (t & 3) * 16;
            const float* sp = (const float*)(sm + AOFF_SP) + q * ATT_SSTR + jg;
            float mx = -1e30f;
            #pragma unroll
            for (int i = 0; i < 16; i++)
                mx = fmaxf(mx, (vdf[jg + i] != 0.f) ? sp[i] : -1e30f);
            mx = fmaxf(mx, __shfl_xor_sync(0xffffffffu, mx, 1));
            mx = fmaxf(mx, __shfl_xor_sync(0xffffffffu, mx, 2));
            if ((t & 3) == 0) {
                float mold = mf[q];
                float mnew = fmaxf(mold, mx);
                mnf[q] = mnew;
                alf[q] = __expf(mold - mnew);
                mf[q]  = mnew;
            }
        }
        __syncthreads();

        // phase 4: P = exp(S - mnew) masked; split Ph/Pl; fused l-update; acc*=alpha
        {
            int q = t >> 2, jg = (t & 3) * 16;
            float* sp = (float*)(sm + AOFF_SP) + q * ATT_SSTR + jg;
            float mn = mnf[q];
            __half2* ph = (__half2*)(sm + AOFF_PH + (q * ATT_PSTR + jg) * 2);
            __half2* pl = (__half2*)(sm + AOFF_PL + (q * ATT_PSTR + jg) * 2);
            float psum = 0.f;
            #pragma unroll
            for (int i = 0; i < 16; i += 2) {
                float e0 = (vdf[jg + i]     != 0.f) ? __expf(sp[i]     - mn) : 0.f;
                float e1 = (vdf[jg + i + 1] != 0.f) ? __expf(sp[i + 1] - mn) : 0.f;
                psum += e0 + e1;
                __half2 hh = __floats2half2_rn(e0, e1);
                __half2 ll = __floats2half2_rn(e0 - __half2float(__low2half(hh)),
                                               e1 - __half2float(__high2half(hh)));
                ph[i >> 1] = hh; pl[i >> 1] = ll;
            }
            psum += __shfl_xor_sync(0xffffffffu, psum, 1);
            psum += __shfl_xor_sync(0xffffffffu, psum, 2);
            if ((t & 3) == 0) lf[q] = lf[q] * alf[q] + psum;
            const int wq = (wid & 3) * 16;
            float a1 = alf[wq + (lane >> 2)];
            float a2 = alf[wq + (lane >> 2) + 8];
            #pragma unroll
            for (int ni = 0; ni < 4; ni++) {
                acc[ni][0] *= a1; acc[ni][1] *= a1;
                acc[ni][2] *= a2; acc[ni][3] *= a2;
            }
        }
        __syncthreads();

        // phase 5: O += P V (2-term fp16, K-dim 64)
        {
            const int wq = (wid & 3) * 16, wd = (wid >> 2) * 32;
            #pragma unroll
            for (int ks = 0; ks < 4; ks++) {
                uint32_t aph[4], apl[4], bv0[4], bv1[4];
                uint32_t aoff = ((wq + (lane & 15)) * ATT_PSTR + ks * 16
                                 + (lane >> 4) * 8) * 2;
                ldsm_x4(aph, sb + AOFF_PH + aoff);
                ldsm_x4(apl, sb + AOFF_PL + aoff);
                uint32_t vrow = ks * 16 + (lane & 15);
                uint32_t v0 = (vrow * ATT_KSTR + wd + (lane >> 4) * 8) * 2;
                uint32_t v1 = (vrow * ATT_KSTR + wd + 16 + (lane >> 4) * 8) * 2;
                ldsm_x4_trans(bv0, sb + AOFF_V + v0);
                ldsm_x4_trans(bv1, sb + AOFF_V + v1);
                mma16816h(acc[0], aph, bv0[0], bv0[1]);
                mma16816h(acc[0], apl, bv0[0], bv0[1]);
                mma16816h(acc[1], aph, bv0[2], bv0[3]);
                mma16816h(acc[1], apl, bv0[2], bv0[3]);
                mma16816h(acc[2], aph, bv1[0], bv1[1]);
                mma16816h(acc[2], apl, bv1[0], bv1[1]);
                mma16816h(acc[3], aph, bv1[2], bv1[3]);
                mma16816h(acc[3], apl, bv1[2], bv1[3]);
            }
        }
        __syncthreads();
    }

    // epilogue: write partials
    {
        const int wq = (wid & 3) * 16, wd = (wid >> 2) * 32;
        size_t pbase = ((((size_t)b * HH + h) * NSPLIT + split) * NLAT) * (size_t)DHD;
        int r = lane >> 2, cc = (lane & 3) * 2;
        #pragma unroll
        for (int ni = 0; ni < 4; ni++) {
            float* d0 = g_pacc + pbase + (size_t)(wq + r) * DHD + wd + ni * 8 + cc;
            float* d1 = g_pacc + pbase + (size_t)(wq + r + 8) * DHD + wd + ni * 8 + cc;
            *(float2*)d0 = make_float2(acc[ni][0], acc[ni][1]);
            *(float2*)d1 = make_float2(acc[ni][2], acc[ni][3]);
        }
    }
    if (t < 64) {
        size_t sbi = (((size_t)b * HH + h) * NSPLIT + split) * NLAT + t;
        g_pm[sbi] = mf[t];
        g_pl[sbi] = lf[t];
    }
}

// ---- pass B: combine split partials -> attn output (b, q, h*64+d) ----
__global__ __launch_bounds__(64) void attn_combine_kernel() {
    int q = blockIdx.x, h = blockIdx.y, b = blockIdx.z;
    int d = threadIdx.x;
    size_t sb = (((size_t)b * HH + h) * NSPLIT) * NLAT + q;
    float mg = -1e30f;
    #pragma unroll
    for (int s = 0; s < NSPLIT; s++) mg = fmaxf(mg, g_pm[sb + (size_t)s * NLAT]);
    float denom = 0.f, a = 0.f;
    #pragma unroll
    for (int s = 0; s < NSPLIT; s++) {
        float w = __expf(g_pm[sb + (size_t)s * NLAT] - mg);
        denom += g_pl[sb + (size_t)s * NLAT] * w;
        a += g_pacc[((((size_t)b * HH + h) * NSPLIT + s) * NLAT + q) * DHD + d] * w;
    }
    g_attnout[((size_t)b * NLAT + q) * INNER + h * DHD + d] = a / denom;
}

extern "C" void kernel_launch(void* const* d_in, const int* in_sizes, int n_in,
                              void* d_out, int out_size) {
    const float* x    = (const float*)d_in[0];
    const float* lat  = (const float*)d_in[1];
    const void*  mask = d_in[2];
    const float* gate = (const float*)d_in[3];
    const float* gm   = (const float*)d_in[4];
    const float* bm   = (const float*)d_in[5];
    const float* gl   = (const float*)d_in[6];
    const float* bl   = (const float*)d_in[7];
    const float* Wq   = (const float*)d_in[8];
    const float* Wk   = (const float*)d_in[9];
    const float* Wv   = (const float*)d_in[10];
    const float* Wout = (const float*)d_in[11];
    float* out = (float*)d_out;

    cudaFuncSetAttribute(kv_mma_kernel,
                         cudaFuncAttributeMaxDynamicSharedMemorySize, GEMM_SMEM);
    cudaFuncSetAttribute(attn_mma_kernel,
                         cudaFuncAttributeMaxDynamicSharedMemorySize, ATT_SMEM);

    // Single stream (R15's fork/join cost more than it overlapped).
    ln_lat_kernel<<<BB * NLAT, 256>>>(lat, gl, bl, (const unsigned int*)mask);
    prep_a_kernel<<<MROWS / 8, 256>>>(x, gm, bm, gate);
    prep_w_kernel<<<dim3(32, 32), 256>>>(Wk, Wv);
    kv_mma_kernel<<<dim3(8, 516), 256, GEMM_SMEM>>>();
    // Q = lat_ln @ Wq, scaled by DIM_HEAD^-0.5 = 0.125
    sgemm_kernel<<<dim3(INNER / 64, (BB * NLAT) / 64), 256>>>(
        Wq, nullptr, BB * NLAT, INNER, DD, DD, INNER, INNER, 0.125f, 0);
    attn_mma_kernel<<<dim3(NSPLIT, HH, BB), 256, ATT_SMEM>>>(mask);
    attn_combine_kernel<<<dim3(NLAT, HH, BB), 64>>>();
    sgemm_kernel<<<dim3(DD / 64, (BB * NLAT) / 64), 256>>>(
        Wout, out, BB * NLAT, DD, INNER, INNER, DD, DD, 1.0f, 1);
}

// round 17
// speedup vs baseline: 1.0626x; 1.0073x over previous
#include <cuda_runtime.h>
#include <cuda_bf16.h>
#include <cuda_fp16.h>
#include <cstdint>

// Problem dims (fixed by the dataset)
#define BB     8
#define FF     8192
#define NLAT   64
#define DD     1024
#define HH     8
#define DHD    64
#define INNER  512
#define KVLEN  (FF + NLAT)          // 8256
#define MROWS  (BB * KVLEN)         // 66048
#define NSPLIT 16
#define JT     64                    // kv tile in attention
#define NTILES (KVLEN / JT)          // 129
#define TPS    ((NTILES + NSPLIT - 1) / NSPLIT)  // 9
#define LN_EPS 1e-5f

// ---------------- family-safe PTX helpers (sm_80-era; no 'a'-features) ------
__device__ __forceinline__ uint32_t smem_u32(const void* p) {
    uint32_t a;
    asm("{ .reg .u64 t; cvta.to.shared.u64 t, %1; cvt.u32.u64 %0, t; }" : "=r"(a) : "l"(p));
    return a;
}
__device__ __forceinline__ void cp_async16(uint32_t dst, const void* src) {
    asm volatile("cp.async.cg.shared.global [%0], [%1], 16;" :: "r"(dst), "l"(src));
}
#define CP_COMMIT() asm volatile("cp.async.commit_group;" ::: "memory")
#define CP_WAIT(n)  asm volatile("cp.async.wait_group %0;" :: "n"(n) : "memory")

__device__ __forceinline__ void ldsm_x4(uint32_t* r, uint32_t addr) {
    asm volatile("ldmatrix.sync.aligned.m8n8.x4.shared.b16 {%0,%1,%2,%3}, [%4];"
        : "=r"(r[0]), "=r"(r[1]), "=r"(r[2]), "=r"(r[3]) : "r"(addr));
}
__device__ __forceinline__ void ldsm_x4_trans(uint32_t* r, uint32_t addr) {
    asm volatile("ldmatrix.sync.aligned.m8n8.x4.trans.shared.b16 {%0,%1,%2,%3}, [%4];"
        : "=r"(r[0]), "=r"(r[1]), "=r"(r[2]), "=r"(r[3]) : "r"(addr));
}
// fp16 mma
__device__ __forceinline__ void mma16816h(float* c, const uint32_t* a,
                                          uint32_t b0, uint32_t b1) {
    asm volatile(
        "mma.sync.aligned.m16n8k16.row.col.f32.f16.f16.f32 "
        "{%0,%1,%2,%3}, {%4,%5,%6,%7}, {%8,%9}, {%0,%1,%2,%3};"
        : "+f"(c[0]), "+f"(c[1]), "+f"(c[2]), "+f"(c[3])
        : "r"(a[0]), "r"(a[1]), "r"(a[2]), "r"(a[3]), "r"(b0), "r"(b1));
}

// -------- scratch (device globals; no allocations allowed) --------
__device__ float          g_lat_ln[BB * NLAT * DD];                       // 2 MB
__device__ __half         g_af[(size_t)MROWS * DD];                       // 135 MB (A fp16)
__device__ __half         g_bf[1024 * 1024];                              // 2 MB  [n][k] fp16
__device__ __half         g_kvf[(size_t)MROWS * 1024];                    // 135 MB (cols 0-511 K, 512-1023 V)
__device__ float          g_qmat[BB * NLAT * INNER];                      // 1 MB
__device__ float          g_attnout[BB * NLAT * INNER];                   // 1 MB
__device__ float          g_pacc[(size_t)BB * HH * NSPLIT * NLAT * DHD];  // 16.8 MB
__device__ float          g_pm[BB * HH * NSPLIT * NLAT];
__device__ float          g_pl[BB * HH * NSPLIT * NLAT];
__device__ int            g_mask_is_byte;

// ---- LayerNorm of latents + (block 0) mask dtype detection ----
__global__ __launch_bounds__(256) void ln_lat_kernel(const float* __restrict__ lat,
                                                     const float* __restrict__ gamma,
                                                     const float* __restrict__ beta,
                                                     const unsigned int* __restrict__ mask_w) {
    int row = blockIdx.x;
    int t = threadIdx.x;
    if (row == 0 && t == 0) {
        unsigned int acc = 0;
        #pragma unroll
        for (int i = 0; i < 64; i++) acc |= mask_w[i];
        g_mask_is_byte = (acc > 1u) ? 1 : 0;
    }
    float4 v = ((const float4*)(lat + (size_t)row * DD))[t];
    __shared__ float rs[256], rq[256];
    rs[t] = v.x + v.y + v.z + v.w;
    rq[t] = v.x*v.x + v.y*v.y + v.z*v.z + v.w*v.w;
    __syncthreads();
    for (int off = 128; off > 0; off >>= 1) {
        if (t < off) { rs[t] += rs[t + off]; rq[t] += rq[t + off]; }
        __syncthreads();
    }
    float mu   = rs[0] * (1.f / DD);
    float var  = rq[0] * (1.f / DD) - mu * mu;
    float rstd = rsqrtf(var + LN_EPS);
    float4 gv = ((const float4*)gamma)[t];
    float4 bv = ((const float4*)beta)[t];
    float4 o;
    o.x = (v.x - mu) * rstd * gv.x + bv.x;
    o.y = (v.y - mu) * rstd * gv.y + bv.y;
    o.z = (v.z - mu) * rstd * gv.z + bv.z;
    o.w = (v.w - mu) * rstd * gv.w + bv.w;
    ((float4*)(g_lat_ln + (size_t)row * DD))[t] = o;
}

// ---- fused LN + fp16 store of A: one row per warp, shuffle reduction ----
__global__ __launch_bounds__(256) void prep_a_kernel(const float* __restrict__ x,
                                                     const float* __restrict__ gm_,
                                                     const float* __restrict__ bm_,
                                                     const float* __restrict__ gate_p) {
    int wid = threadIdx.x >> 5, lane = threadIdx.x & 31;
    int row = blockIdx.x * 8 + wid;       // 0..MROWS-1 (grid = MROWS/8)
    int b = row / KVLEN;
    int r = row - b * KVLEN;
    float4 v[8];
    const float4* src;
    if (r < FF) src = (const float4*)(x + ((size_t)b * FF + r) * DD);
    else        src = (const float4*)(g_lat_ln + ((size_t)b * NLAT + (r - FF)) * DD);
    #pragma unroll
    for (int i = 0; i < 8; i++) v[i] = src[lane + 32 * i];

    if (r < FF) {
        float s = 0.f, q = 0.f;
        #pragma unroll
        for (int i = 0; i < 8; i++) {
            s += v[i].x + v[i].y + v[i].z + v[i].w;
            q += v[i].x*v[i].x + v[i].y*v[i].y + v[i].z*v[i].z + v[i].w*v[i].w;
        }
        #pragma unroll
        for (int off = 16; off > 0; off >>= 1) {
            s += __shfl_xor_sync(0xffffffffu, s, off);
            q += __shfl_xor_sync(0xffffffffu, q, off);
        }
        float mu   = s * (1.f / DD);
        float var  = q * (1.f / DD) - mu * mu;
        float rstd = rsqrtf(var + LN_EPS);
        #pragma unroll
        for (int i = 0; i < 8; i++) {
            float4 gv = ((const float4*)gm_)[lane + 32 * i];
            float4 bv = ((const float4*)bm_)[lane + 32 * i];
            v[i].x = (v[i].x - mu) * rstd * gv.x + bv.x;
            v[i].y = (v[i].y - mu) * rstd * gv.y + bv.y;
            v[i].z = (v[i].z - mu) * rstd * gv.z + bv.z;
            v[i].w = (v[i].w - mu) * rstd * gv.w + bv.w;
        }
    } else {
        float gate = gate_p[0];
        #pragma unroll
        for (int i = 0; i < 8; i++) {
            v[i].x *= gate; v[i].y *= gate; v[i].z *= gate; v[i].w *= gate;
        }
    }
    uint2* dst = (uint2*)(g_af + (size_t)row * DD);
    #pragma unroll
    for (int i = 0; i < 8; i++) {
        __half2 h01 = __floats2half2_rn(v[i].x, v[i].y);
        __half2 h23 = __floats2half2_rn(v[i].z, v[i].w);
        uint2 u;
        u.x = *(uint32_t*)&h01;
        u.y = *(uint32_t*)&h23;
        dst[lane + 32 * i] = u;
    }
}

// ---- transpose [Wk|Wv] (k-major [1024][512] each) into B[n][k] fp16 ----
__global__ __launch_bounds__(256) void prep_w_kernel(const float* __restrict__ Wk,
                                                     const float* __restrict__ Wv) {
    __shared__ float tile[32][33];
    int n0 = blockIdx.x * 32;           // 0..1023 (n of concat)
    int k0 = blockIdx.y * 32;
    int tx = threadIdx.x & 31, ty = threadIdx.x >> 5;  // 32 x 8
    const float* W = (n0 < 512) ? Wk : Wv;
    int nn0 = (n0 < 512) ? n0 : (n0 - 512);
    for (int i = ty; i < 32; i += 8)
        tile[i][tx] = W[(size_t)(k0 + i) * 512 + nn0 + tx];
    __syncthreads();
    for (int i = ty; i < 32; i += 8) {
        float v = tile[tx][i];          // = W[k0+tx][nn0+i]
        g_bf[(size_t)(n0 + i) * 1024 + k0 + tx] = __float2half_rn(v);
    }
}

// ---- HMMA (mma.sync fp16, 1-term) K/V projection: kv = A @ B^T ----
// Legacy-HMMA issue-bound at ~542 us (~94% of the fallback pipe); config is
// the measured local optimum: BM=BN=128, BK=32, 8 warps 32x64, 2 CTAs/SM,
// 5-stage pipeline, prefetch distance 4.
#define AS_STRIDE_H 40                      // halves per SMEM row
#define MAT_BYTES   (128 * AS_STRIDE_H * 2) // 10240 per matrix tile
#define STG_BYTES   (2 * MAT_BYTES)         // 20480 per stage (A, B)
#define NSTAGE      5
#define GEMM_SMEM   (NSTAGE * STG_BYTES)    // 102400
#define NCHUNK      32

__global__ __launch_bounds__(256, 2) void kv_mma_kernel() {
    extern __shared__ char smem[];
    const uint32_t sbase = smem_u32(smem);
    const int t = threadIdx.x;
    const int wid = t >> 5, lane = t & 31;
    const int ntile = blockIdx.x;            // 0..7
    const int mtile = blockIdx.y;            // 0..515
    const size_t arow0 = (size_t)mtile * 128;
    const int    brow0 = ntile * 128;

    // global load assignment: row r_ld, two consecutive 16B segs
    const int r_ld = t >> 1;
    const int seg0 = (t & 1) * 2;            // 0 or 2 (of 4 segs/row)
    const __half* gA = g_af + (arow0 + r_ld) * 1024 + seg0 * 8;
    const __half* gB = g_bf + (size_t)(brow0 + r_ld) * 1024 + seg0 * 8;
    const uint32_t sAdst = sbase + r_ld * 80 + seg0 * 16;

    #define LOAD_CHUNK(chunk, stg_) do {                                       \
        uint32_t sb_ = sAdst + (stg_) * STG_BYTES;                             \
        int ko_ = (chunk) * 32;                                                \
        cp_async16(sb_,                  gA + ko_);                            \
        cp_async16(sb_ + 16,             gA + ko_ + 8);                        \
        cp_async16(sb_ + MAT_BYTES,      gB + ko_);                            \
        cp_async16(sb_ + MAT_BYTES + 16, gB + ko_ + 8);                        \
    } while (0)

    // warp tile: wm in {0,32,64,96}, wn in {0,64}
    const int wm = (wid & 3) * 32;
    const int wn = (wid >> 2) * 64;

    const int a_off_h = (wm + (lane & 15)) * AS_STRIDE_H + (lane >> 4) * 8;
    const int b_off_h = (wn + (lane & 7) + ((lane >> 3) & 1) * 8) * AS_STRIDE_H
                        + (lane >> 4) * 8;

    float acc[2][8][4];
    #pragma unroll
    for (int i = 0; i < 2; i++)
        #pragma unroll
        for (int j = 0; j < 8; j++)
            #pragma unroll
            for (int c = 0; c < 4; c++) acc[i][j][c] = 0.f;

    LOAD_CHUNK(0, 0); CP_COMMIT();
    LOAD_CHUNK(1, 1); CP_COMMIT();
    LOAD_CHUNK(2, 2); CP_COMMIT();
    LOAD_CHUNK(3, 3); CP_COMMIT();

    int st = 0;  // stage of current chunk
    for (int chunk = 0; chunk < NCHUNK; chunk++) {
        if (chunk < NCHUNK - 3)       { CP_WAIT(3); }
        else if (chunk == NCHUNK - 3) { CP_WAIT(2); }
        else if (chunk == NCHUNK - 2) { CP_WAIT(1); }
        else                          { CP_WAIT(0); }
        __syncthreads();   // also protects WAR on the stage being refilled
        if (chunk + 4 < NCHUNK) {
            int stn = st + 4; if (stn >= NSTAGE) stn -= NSTAGE;
            LOAD_CHUNK(chunk + 4, stn);
            CP_COMMIT();
        }

        const uint32_t stg = sbase + st * STG_BYTES;
        #pragma unroll
        for (int ks = 0; ks < 2; ks++) {
            uint32_t a[2][4];
            #pragma unroll
            for (int mi = 0; mi < 2; mi++) {
                uint32_t ao = stg + (a_off_h + mi * 16 * AS_STRIDE_H + ks * 16) * 2;
                ldsm_x4(a[mi], ao);
            }
            #pragma unroll
            for (int nip = 0; nip < 4; nip++) {
                uint32_t bb[4];
                uint32_t bo = stg + MAT_BYTES
                            + (b_off_h + nip * 16 * AS_STRIDE_H + ks * 16) * 2;
                ldsm_x4(bb, bo);
                #pragma unroll
                for (int mi = 0; mi < 2; mi++) {
                    mma16816h(acc[mi][nip * 2],     a[mi], bb[0], bb[2]);
                    mma16816h(acc[mi][nip * 2 + 1], a[mi], bb[1], bb[3]);
                }
            }
        }
        if (++st == NSTAGE) st = 0;
    }

    // epilogue: write kv as single fp16
    const int col0 = ntile * 128 + wn + (lane & 3) * 2;
    #pragma unroll
    for (int mi = 0; mi < 2; mi++) {
        size_t row = arow0 + wm + mi * 16 + (lane >> 2);
        #pragma unroll
        for (int ni = 0; ni < 8; ni++) {
            size_t o0 = row * 1024 + col0 + ni * 8;
            size_t o1 = (row + 8) * 1024 + col0 + ni * 8;
            *(__half2*)(g_kvf + o0) = __floats2half2_rn(acc[mi][ni][0], acc[mi][ni][1]);
            *(__half2*)(g_kvf + o1) = __floats2half2_rn(acc[mi][ni][2], acc[mi][ni][3]);
        }
    }
}

// ---- generic small sgemm (mode 0: Q proj, mode 1: out proj) ----
__global__ __launch_bounds__(256) void sgemm_kernel(const float* __restrict__ Bmat,
                                                    float* __restrict__ Cext,
                                                    int M, int N, int K,
                                                    int lda, int ldb, int ldc,
                                                    float alpha, int mode) {
    const float* A = (mode == 0) ? g_lat_ln : g_attnout;
    float* C = (mode == 0) ? g_qmat : Cext;
    __shared__ float As[16][65];
    __shared__ float Bs[16][65];
    int t = threadIdx.x;
    int tx = t & 15, ty = t >> 4;
    int n0 = blockIdx.x * 64;
    int m0 = blockIdx.y * 64;
    float acc[4][4] = {};
    for (int k0 = 0; k0 < K; k0 += 16) {
        #pragma unroll
        for (int l = 0; l < 4; l++) {
            int idx = t + l * 256;
            int row = idx >> 4, kk = idx & 15;
            As[kk][row] = A[(size_t)(m0 + row) * lda + k0 + kk];
        }
        #pragma unroll
        for (int l = 0; l < 4; l++) {
            int idx = t + l * 256;
            int kk = idx >> 6, col = idx & 63;
            Bs[kk][col] = Bmat[(size_t)(k0 + kk) * ldb + n0 + col];
        }
        __syncthreads();
        #pragma unroll
        for (int kk = 0; kk < 16; kk++) {
            float a[4], bb[4];
            #pragma unroll
            for (int i = 0; i < 4; i++) a[i]  = As[kk][ty * 4 + i];
            #pragma unroll
            for (int j = 0; j < 4; j++) bb[j] = Bs[kk][tx * 4 + j];
            #pragma unroll
            for (int i = 0; i < 4; i++)
                #pragma unroll
                for (int j = 0; j < 4; j++)
                    acc[i][j] = fmaf(a[i], bb[j], acc[i][j]);
        }
        __syncthreads();
    }
    #pragma unroll
    for (int i = 0; i < 4; i++)
        #pragma unroll
        for (int j = 0; j < 4; j++)
            C[(size_t)(m0 + ty * 4 + i) * ldc + n0 + tx * 4 + j] = alpha * acc[i][j];
}

// ---- split-KV flash attention, fp16 HMMA, JT=64 ----
// Q split fp16 hi/lo (exact to 2^-22); K,V single fp16; P split fp16 hi/lo.
// SMEM cut to 56576 B by overlaying the P hi/lo buffers onto the (dead after
// phase 4) S buffer: phase 4 register-buffers the exp values, barriers, then
// writes P. 4 CTAs/SM (was 3) -> 1.73 waves instead of 2.31.
#define ATT_QSTR 72
#define ATT_KSTR 72
#define ATT_PSTR 72
#define ATT_SSTR 72
#define AOFF_QH 0
#define AOFF_QL 9216
#define AOFF_K  18432
#define AOFF_V  27648
#define AOFF_SP 36864
#define AOFF_PH 36864
#define AOFF_PL 46080
#define AOFF_M  55296
#define AOFF_L  55552
#define AOFF_AL 55808
#define AOFF_MN 56064
#define AOFF_VD 56320
#define ATT_SMEM 56576

__global__ __launch_bounds__(256, 4) void attn_mma_kernel(const void* __restrict__ mask_raw) {
    extern __shared__ char sm[];
    const uint32_t sb = smem_u32(sm);
    const int split = blockIdx.x, h = blockIdx.y, b = blockIdx.z;
    const int t = threadIdx.x, wid = t >> 5, lane = t & 31;
    const unsigned char* mask8 = (const unsigned char*)mask_raw;
    const int*           mask32 = (const int*)mask_raw;
    const int is_byte = g_mask_is_byte;

    float* mf  = (float*)(sm + AOFF_M);
    float* lf  = (float*)(sm + AOFF_L);
    float* alf = (float*)(sm + AOFF_AL);
    float* mnf = (float*)(sm + AOFF_MN);
    float* vdf = (float*)(sm + AOFF_VD);

    // prologue: load+split Q slice (64q x 64d) to Qh/Ql (fp16 hi/lo)
    {
        int q = t >> 2, dg = (t & 3) * 16;
        const float4* src = (const float4*)(g_qmat + ((size_t)(b * NLAT + q)) * INNER
                                            + h * DHD + dg);
        __half2* qh = (__half2*)(sm + AOFF_QH + (q * ATT_QSTR + dg) * 2);
        __half2* ql = (__half2*)(sm + AOFF_QL + (q * ATT_QSTR + dg) * 2);
        #pragma unroll
        for (int i = 0; i < 4; i++) {
            float4 v = src[i];
            __half2 h01 = __floats2half2_rn(v.x, v.y);
            __half2 h23 = __floats2half2_rn(v.z, v.w);
            __half2 l01 = __floats2half2_rn(v.x - __half2float(__low2half(h01)),
                                            v.y - __half2float(__high2half(h01)));
            __half2 l23 = __floats2half2_rn(v.z - __half2float(__low2half(h23)),
                                            v.w - __half2float(__high2half(h23)));
            qh[i * 2] = h01; qh[i * 2 + 1] = h23;
            ql[i * 2] = l01; ql[i * 2 + 1] = l23;
        }
    }
    if (t < 64) { mf[t] = -1e30f; lf[t] = 0.f; }

    float acc[4][4];
    #pragma unroll
    for (int i = 0; i < 4; i++)
        #pragma unroll
        for (int j = 0; j < 4; j++) acc[i][j] = 0.f;

    const int t0 = split * TPS;
    int tcnt = NTILES - t0;
    if (tcnt > TPS) tcnt = TPS;
    if (tcnt < 0) tcnt = 0;
    __syncthreads();

    for (int it = 0; it < tcnt; it++) {
        const int j0 = (t0 + it) * JT;
        // phase 1: K/V fp16 tiles (64 rows x 64 cols each), 2 segs/thread/array
        {
            int seg = (t & 7) * 8;         // halves
            #pragma unroll
            for (int it2 = 0; it2 < 2; it2++) {
                int row = (t >> 3) + it2 * 32;
                const __half* src = g_kvf + ((size_t)b * KVLEN + j0 + row) * 1024;
                uint32_t doff = (uint32_t)(row * ATT_KSTR + seg) * 2;
                *(uint4*)(sm + AOFF_K + doff) = *(const uint4*)(src + h * DHD + seg);
                *(uint4*)(sm + AOFF_V + doff) = *(const uint4*)(src + 512 + h * DHD + seg);
            }
        }
        if (t < JT) {
            int row = j0 + t;
            bool valid;
            if (row >= FF) valid = true;
            else {
                int mv = is_byte ? (int)mask8[b * FF + row] : mask32[b * FF + row];
                valid = (mv == 0);
            }
            vdf[t] = valid ? 1.f : 0.f;
        }
        __syncthreads();

        // phase 2: S = Q K^T (2-term fp16), warp tile 16q x 32j, write SP[q][j]
        {
            const int wq = (wid & 3) * 16, wj = (wid >> 2) * 32;
            float c[4][4];
            #pragma unroll
            for (int jb = 0; jb < 4; jb++)
                #pragma unroll
                for (int cc2 = 0; cc2 < 4; cc2++) c[jb][cc2] = 0.f;
            #pragma unroll
            for (int ks = 0; ks < 4; ks++) {
                uint32_t aqh[4], aql[4], bk0[4], bk1[4];
                uint32_t aoff = ((wq + (lane & 15)) * ATT_QSTR + ks * 16
                                 + (lane >> 4) * 8) * 2;
                ldsm_x4(aqh, sb + AOFF_QH + aoff);
                ldsm_x4(aql, sb + AOFF_QL + aoff);
                uint32_t brow = (lane & 7) + ((lane >> 3) & 1) * 8;
                uint32_t bo0 = ((wj + brow) * ATT_KSTR + ks * 16 + (lane >> 4) * 8) * 2;
                uint32_t bo1 = ((wj + 16 + brow) * ATT_KSTR + ks * 16 + (lane >> 4) * 8) * 2;
                ldsm_x4(bk0, sb + AOFF_K + bo0);
                ldsm_x4(bk1, sb + AOFF_K + bo1);
                mma16816h(c[0], aqh, bk0[0], bk0[2]);
                mma16816h(c[0], aql, bk0[0], bk0[2]);
                mma16816h(c[1], aqh, bk0[1], bk0[3]);
                mma16816h(c[1], aql, bk0[1], bk0[3]);
                mma16816h(c[2], aqh, bk1[0], bk1[2]);
                mma16816h(c[2], aql, bk1[0], bk1[2]);
                mma16816h(c[3], aqh, bk1[1], bk1[3]);
                mma16816h(c[3], aql, bk1[1], bk1[3]);
            }
            float* sp = (float*)(sm + AOFF_SP);
            int r = lane >> 2, cc = (lane & 3) * 2;
            #pragma unroll
            for (int jb = 0; jb < 4; jb++) {
                *(float2*)&sp[(wq + r) * ATT_SSTR + wj + jb * 8 + cc] =
                    make_float2(c[jb][0], c[jb][1]);
                *(float2*)&sp[(wq + r + 8) * ATT_SSTR + wj + jb * 8 + cc] =
                    make_float2(c[jb][2], c[jb][3]);
            }
        }
        __syncthreads();

        // phase 3: masked row max -> mnew, alpha (4 threads/row + shfl)
        {
            int q = t >> 2, jg = (t & 3) * 16;
            const float* sp = (const float*)(sm + AOFF_SP) + q * ATT_SSTR + jg;
            float mx = -1e30f;
            #pragma unroll
            for (int i = 0; i < 16; i++)
                mx = fmaxf(mx, (vdf[jg + i] != 0.f) ? sp[i] : -1e30f);
            mx = fmaxf(mx, __shfl_xor_sync(0xffffffffu, mx, 1));
            mx = fmaxf(mx, __shfl_xor_sync(0xffffffffu, mx, 2));
            if ((t & 3) == 0) {
                float mold = mf[q];
                float mnew = fmaxf(mold, mx);
                mnf[q] = mnew;
                alf[q] = __expf(mold - mnew);
                mf[q]  = mnew;
            }
        }
        __syncthreads();

        // phase 4a: read S, compute exp into registers; fused l-update; acc*=alpha
        float ev[16];
        {
            int q = t >> 2, jg = (t & 3) * 16;
            const float* sp = (const float*)(sm + AOFF_SP) + q * ATT_SSTR + jg;
            float mn = mnf[q];
            float psum = 0.f;
            #pragma unroll
            for (int i = 0; i < 16; i++) {
                float e = (vdf[jg + i] != 0.f) ? __expf(sp[i] - mn) : 0.f;
                ev[i] = e;
                psum += e;
            }
            psum += __shfl_xor_sync(0xffffffffu, psum, 1);
            psum += __shfl_xor_sync(0xffffffffu, psum, 2);
            if ((t & 3) == 0) lf[q] = lf[q] * alf[q] + psum;
            const int wq = (wid & 3) * 16;
            float a1 = alf[wq + (lane >> 2)];
            float a2 = alf[wq + (lane >> 2) + 8];
            #pragma unroll
            for (int ni = 0; ni < 4; ni++) {
                acc[ni][0] *= a1; acc[ni][1] *= a1;
                acc[ni][2] *= a2; acc[ni][3] *= a2;
            }
        }
        __syncthreads();   // all SP reads done; PH/PL may now overwrite SP bytes

        // phase 4b: split exp values to Ph/Pl (fp16), overlaid on SP region
        {
            int q = t >> 2, jg = (t & 3) * 16;
            __half2* ph = (__half2*)(sm + AOFF_PH + (q * ATT_PSTR + jg) * 2);
            __half2* pl = (__half2*)(sm + AOFF_PL + (q * ATT_PSTR + jg) * 2);
            #pragma unroll
            for (int i = 0; i < 16; i += 2) {
                __half2 hh = __floats2half2_rn(ev[i], ev[i + 1]);
                __half2 ll = __floats2half2_rn(ev[i]     - __half2float(__low2half(hh)),
                                               ev[i + 1] - __half2float(__high2half(hh)));
                ph[i >> 1] = hh; pl[i >> 1] = ll;
            }
        }
        __syncthreads();

        // phase 5: O += P V (2-term fp16, K-dim 64)
        {
            const int wq = (wid & 3) * 16, wd = (wid >> 2) * 32;
            #pragma unroll
            for (int ks = 0; ks < 4; ks++) {
                uint32_t aph[4], apl[4], bv0[4], bv1[4];
                uint32_t aoff = ((wq + (lane & 15)) * ATT_PSTR + ks * 16
                                 + (lane >> 4) * 8) * 2;
                ldsm_x4(aph, sb + AOFF_PH + aoff);
                ldsm_x4(apl, sb + AOFF_PL + aoff);
                uint32_t vrow = ks * 16 + (lane & 15);
                uint32_t v0 = (vrow * ATT_KSTR + wd + (lane >> 4) * 8) * 2;
                uint32_t v1 = (vrow * ATT_KSTR + wd + 16 + (lane >> 4) * 8) * 2;
                ldsm_x4_trans(bv0, sb + AOFF_V + v0);
                ldsm_x4_trans(bv1, sb + AOFF_V + v1);
                mma16816h(acc[0], aph, bv0[0], bv0[1]);
                mma16816h(acc[0], apl, bv0[0], bv0[1]);
                mma16816h(acc[1], aph, bv0[2], bv0[3]);
                mma16816h(acc[1], apl, bv0[2], bv0[3]);
                mma16816h(acc[2], aph, bv1[0], bv1[1]);
                mma16816h(acc[2], apl, bv1[0], bv1[1]);
                mma16816h(acc[3], aph, bv1[2], bv1[3]);
                mma16816h(acc[3], apl, bv1[2], bv1[3]);
            }
        }
        __syncthreads();
    }

    // epilogue: write partials
    {
        const int wq = (wid & 3) * 16, wd = (wid >> 2) * 32;
        size_t pbase = ((((size_t)b * HH + h) * NSPLIT + split) * NLAT) * (size_t)DHD;
        int r = lane >> 2, cc = (lane & 3) * 2;
        #pragma unroll
        for (int ni = 0; ni < 4; ni++) {
            float* d0 = g_pacc + pbase + (size_t)(wq + r) * DHD + wd + ni * 8 + cc;
            float* d1 = g_pacc + pbase + (size_t)(wq + r + 8) * DHD + wd + ni * 8 + cc;
            *(float2*)d0 = make_float2(acc[ni][0], acc[ni][1]);
            *(float2*)d1 = make_float2(acc[ni][2], acc[ni][3]);
        }
    }
    if (t < 64) {
        size_t sbi = (((size_t)b * HH + h) * NSPLIT + split) * NLAT + t;
        g_pm[sbi] = mf[t];
        g_pl[sbi] = lf[t];
    }
}

// ---- pass B: combine split partials -> attn output (b, q, h*64+d) ----
__global__ __launch_bounds__(64) void attn_combine_kernel() {
    int q = blockIdx.x, h = blockIdx.y, b = blockIdx.z;
    int d = threadIdx.x;
    size_t sb = (((size_t)b * HH + h) * NSPLIT) * NLAT + q;
    float mg = -1e30f;
    #pragma unroll
    for (int s = 0; s < NSPLIT; s++) mg = fmaxf(mg, g_pm[sb + (size_t)s * NLAT]);
    float denom = 0.f, a = 0.f;
    #pragma unroll
    for (int s = 0; s < NSPLIT; s++) {
        float w = __expf(g_pm[sb + (size_t)s * NLAT] - mg);
        denom += g_pl[sb + (size_t)s * NLAT] * w;
        a += g_pacc[((((size_t)b * HH + h) * NSPLIT + s) * NLAT + q) * DHD + d] * w;
    }
    g_attnout[((size_t)b * NLAT + q) * INNER + h * DHD + d] = a / denom;
}

extern "C" void kernel_launch(void* const* d_in, const int* in_sizes, int n_in,
                              void* d_out, int out_size) {
    const float* x    = (const float*)d_in[0];
    const float* lat  = (const float*)d_in[1];
    const void*  mask = d_in[2];
    const float* gate = (const float*)d_in[3];
    const float* gm   = (const float*)d_in[4];
    const float* bm   = (const float*)d_in[5];
    const float* gl   = (const float*)d_in[6];
    const float* bl   = (const float*)d_in[7];
    const float* Wq   = (const float*)d_in[8];
    const float* Wk   = (const float*)d_in[9];
    const float* Wv   = (const float*)d_in[10];
    const float* Wout = (const float*)d_in[11];
    float* out = (float*)d_out;

    cudaFuncSetAttribute(kv_mma_kernel,
                         cudaFuncAttributeMaxDynamicSharedMemorySize, GEMM_SMEM);
    cudaFuncSetAttribute(attn_mma_kernel,
                         cudaFuncAttributeMaxDynamicSharedMemorySize, ATT_SMEM);

    ln_lat_kernel<<<BB * NLAT, 256>>>(lat, gl, bl, (const unsigned int*)mask);
    prep_a_kernel<<<MROWS / 8, 256>>>(x, gm, bm, gate);
    prep_w_kernel<<<dim3(32, 32), 256>>>(Wk, Wv);
    kv_mma_kernel<<<dim3(8, 516), 256, GEMM_SMEM>>>();
    // Q = lat_ln @ Wq, scaled by DIM_HEAD^-0.5 = 0.125
    sgemm_kernel<<<dim3(INNER / 64, (BB * NLAT) / 64), 256>>>(
        Wq, nullptr, BB * NLAT, INNER, DD, DD, INNER, INNER, 0.125f, 0);
    attn_mma_kernel<<<dim3(NSPLIT, HH, BB), 256, ATT_SMEM>>>(mask);
    attn_combine_kernel<<<dim3(NLAT, HH, BB), 64>>>();
    sgemm_kernel<<<dim3(DD / 64, (BB * NLAT) / 64), 256>>>(
        Wout, out, BB * NLAT, DD, INNER, INNER, DD, DD, 1.0f, 1);
}